// round 12
// baseline (speedup 1.0000x reference)
#include <cuda_runtime.h>
#include <cuda_fp16.h>
#include <cstdint>

#define Bsz 2
#define S   2048
#define D   1024
#define H   16
#define HD  64

// ---------------- scratch (__device__ globals; alloc-free rule) -------------
__device__ __half g_xh[(size_t)Bsz * S * D];        // x fp16 single
__device__ __half g_w1[(size_t)2 * D * D];          // in_proj_w[0:2D] fp16 single
__device__ __half g_w3[(size_t)D * D];              // out_w fp16 single
__device__ __half g_qk[(size_t)Bsz * S * 2 * D];    // Q (scaled 0.125*log2e) | K, fp16 single
__device__ __half g_vh[(size_t)Bsz * S * D];        // V fp16 single
__device__ __align__(16) uint32_t g_mh[4194304];    // fp16 {0,1} mask in a-frag order
__device__ __half g_ath[(size_t)Bsz * S * D];       // attention out fp16 single

// ---------------- helpers (all plain sm_80+ PTX; no 'a' features) -----------
__device__ __forceinline__ uint32_t smem_u32(const void* p) {
    uint32_t a;
    asm("{ .reg .u64 t; cvta.to.shared.u64 t, %1; cvt.u32.u64 %0, t; }" : "=r"(a) : "l"(p));
    return a;
}
__device__ __forceinline__ void cp16(uint32_t dst, const void* src) {
    asm volatile("cp.async.cg.shared.global [%0], [%1], 16;" :: "r"(dst), "l"(src));
}
__device__ __forceinline__ void cp_commit() {
    asm volatile("cp.async.commit_group;" ::: "memory");
}
__device__ __forceinline__ void cp_wait0() {
    asm volatile("cp.async.wait_group 0;" ::: "memory");
}
__device__ __forceinline__ void cp_wait1() {
    asm volatile("cp.async.wait_group 1;" ::: "memory");
}
__device__ __forceinline__ void ldsm_x4(uint32_t (&r)[4], uint32_t addr) {
    asm volatile("ldmatrix.sync.aligned.m8n8.x4.shared.b16 {%0,%1,%2,%3}, [%4];"
                 : "=r"(r[0]), "=r"(r[1]), "=r"(r[2]), "=r"(r[3]) : "r"(addr));
}
__device__ __forceinline__ void ldsm_x4_t(uint32_t (&r)[4], uint32_t addr) {
    asm volatile("ldmatrix.sync.aligned.m8n8.x4.trans.shared.b16 {%0,%1,%2,%3}, [%4];"
                 : "=r"(r[0]), "=r"(r[1]), "=r"(r[2]), "=r"(r[3]) : "r"(addr));
}
__device__ __forceinline__ void mma16816h(float (&c)[4], const uint32_t (&a)[4],
                                          uint32_t b0, uint32_t b1) {
    asm volatile(
        "mma.sync.aligned.m16n8k16.row.col.f32.f16.f16.f32 "
        "{%0,%1,%2,%3}, {%4,%5,%6,%7}, {%8,%9}, {%0,%1,%2,%3};"
        : "+f"(c[0]), "+f"(c[1]), "+f"(c[2]), "+f"(c[3])
        : "r"(a[0]), "r"(a[1]), "r"(a[2]), "r"(a[3]), "r"(b0), "r"(b1));
}
__device__ __forceinline__ uint32_t h2pack_sat(float lo, float hi) {
    uint32_t r;
    asm("cvt.rn.satfinite.f16x2.f32 %0, %1, %2;" : "=r"(r) : "f"(hi), "f"(lo));
    return r;
}
__device__ __forceinline__ uint32_t hmul2u(uint32_t a, uint32_t b) {
    __half2 ha = *reinterpret_cast<__half2*>(&a);
    __half2 hb = *reinterpret_cast<__half2*>(&b);
    __half2 hc = __hmul2(ha, hb);
    return *reinterpret_cast<uint32_t*>(&hc);
}
__device__ __forceinline__ float ex2(float x) {
    float r;
    asm("ex2.approx.f32 %0, %1;" : "=f"(r) : "f"(x));
    return r;
}
__device__ __forceinline__ void single_store_h(__half* Oh, size_t idx,
                                               float v0, float v1) {
    __half2 a; a.x = __float2half_rn(v0); a.y = __float2half_rn(v1);
    *(__half2*)(Oh + idx) = a;
}

// ---------------------------------------------------------------------------
// Fused conversions: x, w1, w3, V -> fp16 single.
// ---------------------------------------------------------------------------
#define CN1 1048576   // x  float4s
#define CN2 524288    // w1
#define CN3 262144    // w3
#define CN4 1048576   // V
#define CNT (CN1 + CN2 + CN3 + CN4)

__global__ __launch_bounds__(256)
void conv_all(const float* __restrict__ x, const float* __restrict__ w1,
              const float* __restrict__ w3, const float* __restrict__ Vin) {
    int i = blockIdx.x * 256 + threadIdx.x;
    if (i >= CNT) return;
    int j = i;
    const float* src;
    __half* o;
    if (j < CN1) { src = x; o = g_xh; }
    else if ((j -= CN1) < CN2) { src = w1; o = g_w1; }
    else if ((j -= CN2) < CN3) { src = w3; o = g_w3; }
    else { j -= CN3; src = Vin; o = g_vh; }
    float4 v = *(const float4*)(src + (size_t)j * 4);
    single_store_h(o, (size_t)j * 4, v.x, v.y);
    single_store_h(o, (size_t)j * 4 + 2, v.z, v.w);
}

// ---------------------------------------------------------------------------
// Mask pre-pass: expand M to fp16 {0,1} words laid out in attention's exact
// per-thread a-frag order. Word index = ((((b*16+qt)*8+wid)*32+it)*32+lane)*16
//  + (jg>>1)*4 + (jg&1)*2 + s, value = {M[row+8s][col(jg)], M[row+8s][col+1]}.
// ---------------------------------------------------------------------------
__global__ __launch_bounds__(256)
void mask_pre(const float* __restrict__ Min) {
    int idx = blockIdx.x * 256 + threadIdx.x;   // 262144 total (2^18)
    int lane = idx & 31, it = (idx >> 5) & 31, wid = (idx >> 10) & 7;
    int qt = (idx >> 13) & 15, b = idx >> 17;
    int row = b * S + qt * 128 + wid * 16 + (lane >> 2);
    int col = it * 64 + (lane & 3) * 2;
    const float* base = Min + (size_t)row * S + col;
    uint32_t w[16];
    #pragma unroll
    for (int j = 0; j < 8; j++) {
        float2 a = *(const float2*)(base + j * 8);
        float2 c = *(const float2*)(base + (size_t)8 * S + j * 8);
        uint32_t wa = (a.x != 0.f ? 0x3C00u : 0u) | (a.y != 0.f ? 0x3C000000u : 0u);
        uint32_t wc = (c.x != 0.f ? 0x3C00u : 0u) | (c.y != 0.f ? 0x3C000000u : 0u);
        w[(j >> 1) * 4 + (j & 1) * 2 + 0] = wa;
        w[(j >> 1) * 4 + (j & 1) * 2 + 1] = wc;
    }
    uint4* dst = (uint4*)(g_mh + (size_t)idx * 16);
    dst[0] = make_uint4(w[0], w[1], w[2], w[3]);
    dst[1] = make_uint4(w[4], w[5], w[6], w[7]);
    dst[2] = make_uint4(w[8], w[9], w[10], w[11]);
    dst[3] = make_uint4(w[12], w[13], w[14], w[15]);
}

// ---------------------------------------------------------------------------
// fp16 single GEMM: C = A[M][K] * B[N][K]^T + bias
// 128x128 tile, BK=32, cp.async double-buffered, 8 warps (2x4).
// mode 0: fp32 out to Cf. mode 1: fp16 single out; Q cols scaled 0.125*log2e.
// ---------------------------------------------------------------------------
#define GEMM_SMEM (2 * 10240 * 2)
#define QSC 0.1803368801111204f   // 0.125 * log2(e)

__device__ __forceinline__ void gemm_issue(
    const __half* A, const __half* Bw,
    int K, int row0, int col0, int chunk, uint32_t dstbase, int tid) {
    #pragma unroll
    for (int j = 0; j < 4; j++) {
        int linear = tid + j * 256;
        int arr = linear >> 9, rem = linear & 511;
        int r = rem >> 2, c = rem & 3;
        const __half* src = arr ? Bw : A;
        int grow = (arr ? col0 : row0) + r;
        cp16(dstbase + (uint32_t)(arr * 5120 + r * 40 + c * 8) * 2,
             src + (size_t)grow * K + chunk * 32 + c * 8);
    }
}

__global__ __launch_bounds__(256, 2)
void mma_gemm(const __half* __restrict__ A, const __half* __restrict__ Bw,
              const float* __restrict__ bias, float* __restrict__ Cf,
              __half* __restrict__ Oh, int K, int N, int mode) {
    extern __shared__ __half smem[];
    const int tid = threadIdx.x;
    const int wid = tid >> 5, lane = tid & 31;
    const int wr = wid >> 2, wc = wid & 3;
    const int row0 = blockIdx.y * 128, col0 = blockIdx.x * 128;
    const uint32_t sb = smem_u32(smem);

    float acc[4][4][4] = {};

    gemm_issue(A, Bw, K, row0, col0, 0, sb, tid);
    cp_commit();

    const int nch = K / 32;
    for (int ch = 0; ch < nch; ++ch) {
        const int p = ch & 1;
        if (ch + 1 < nch) {
            gemm_issue(A, Bw, K, row0, col0, ch + 1, sb + (p ^ 1) * 20480, tid);
            cp_commit();
            cp_wait1();
        } else {
            cp_wait0();
        }
        __syncthreads();

        const uint32_t bufb = sb + p * 20480;
        #pragma unroll
        for (int kk = 0; kk < 2; kk++) {
            const uint32_t koffs = (uint32_t)(kk * 16 + (lane >> 4) * 8);
            uint32_t b0[4], b1[4];
            ldsm_x4(b0, bufb + (5120u + (uint32_t)((wc * 32 + (lane & 15)) * 40) + koffs) * 2);
            ldsm_x4(b1, bufb + (5120u + (uint32_t)((wc * 32 + 16 + (lane & 15)) * 40) + koffs) * 2);
            #pragma unroll
            for (int i = 0; i < 4; i++) {
                uint32_t a4[4];
                ldsm_x4(a4, bufb + ((uint32_t)((wr * 64 + i * 16 + (lane & 15)) * 40) + koffs) * 2);
                mma16816h(acc[i][0], a4, b0[0], b0[2]);
                mma16816h(acc[i][1], a4, b0[1], b0[3]);
                mma16816h(acc[i][2], a4, b1[0], b1[2]);
                mma16816h(acc[i][3], a4, b1[1], b1[3]);
            }
        }
        __syncthreads();
    }

    const float qs = (mode == 1 && col0 < D) ? QSC : 1.0f;
    #pragma unroll
    for (int j = 0; j < 4; j++) {
        const int col = col0 + wc * 32 + j * 8 + (lane & 3) * 2;
        const float b0 = bias[col], b1 = bias[col + 1];
        #pragma unroll
        for (int i = 0; i < 4; i++) {
            const int row = row0 + wr * 64 + i * 16 + (lane >> 2);
            float v0 = (acc[i][j][0] + b0) * qs, v1 = (acc[i][j][1] + b1) * qs;
            float w0 = (acc[i][j][2] + b0) * qs, w1 = (acc[i][j][3] + b1) * qs;
            if (mode == 0) {
                *(float2*)(Cf + (size_t)row * N + col) = make_float2(v0, v1);
                *(float2*)(Cf + (size_t)(row + 8) * N + col) = make_float2(w0, w1);
            } else {
                single_store_h(Oh, (size_t)row * N + col, v0, v1);
                single_store_h(Oh, (size_t)(row + 8) * N + col, w0, w1);
            }
        }
    }
}

// ---------------------------------------------------------------------------
// Attention (fp16 mma). Per CTA: 128 q rows; 8 warps x 16q x 64k per iter,
// processed in two 32-key halves (halves sc live range -> regs for masks).
// Scores = Q·K (Q pre-scaled 0.125*log2e; e = ex2(s)); Q frags hoisted.
// Mask applied as fp16 {0,1} HMUL2 on packed P (satfinite pack: no inf*0).
// Zm accumulated by tensor core: Oz += P x ones-B (no scalar FADDs, no shfl).
// 3-deep KV ring -> ONE barrier per iteration.
// smem halves: Q@0 (9216), 3 KV buffers @9216 stride 9216 (K@0, V@4608).
// ---------------------------------------------------------------------------
#define ATTN_SMEM ((9216 + 3 * 9216) * 2)

__device__ __forceinline__ void attn_issue_kv(int b, int h, int it, uint32_t sb,
                                              int p, int tid) {
    const int k0 = it * 64;
    #pragma unroll
    for (int j = 0; j < 4; j++) {
        int linear = tid + j * 256;
        int arr = linear >> 9, rem = linear & 511;
        int r = rem >> 3, c = rem & 7;
        const __half* src = arr
            ? g_vh + (size_t)(b * S + k0 + r) * 1024 + h * 64 + c * 8
            : g_qk + (size_t)(b * S + k0 + r) * 2048 + D + h * 64 + c * 8;
        cp16(sb + (uint32_t)(9216 + p * 9216 + arr * 4608 + r * 72 + c * 8) * 2, src);
    }
}

__global__ __launch_bounds__(256, 2)
void attn_mma() {
    extern __shared__ __half smh[];
    const int tid = threadIdx.x;
    const int wid = tid >> 5, lane = tid & 31;
    const int b = blockIdx.z, h = blockIdx.y;
    const int q0 = blockIdx.x * 128;
    const uint32_t sb = smem_u32(smh);
    const uint32_t ONE2 = 0x3C003C00u;   // fp16 {1,1}

    // Q -> smem (same commit group as iter-0 K/V)
    #pragma unroll
    for (int j = 0; j < 4; j++) {
        int linear = tid + j * 256;
        int r = linear >> 3, c = linear & 7;
        cp16(sb + (uint32_t)(r * 72 + c * 8) * 2,
             g_qk + (size_t)(b * S + q0 + r) * 2048 + h * 64 + c * 8);
    }
    attn_issue_kv(b, h, 0, sb, 0, tid);
    cp_commit();

    float Oc[8][4] = {};
    float Oz[4] = {};
    uint32_t qh[4][4];
    int p = 0;

    const uint32_t qrow_off = (uint32_t)((wid * 16 + (lane & 15)) * 72 + (lane >> 4) * 8);
    const uint32_t* mhp = g_mh
        + ((size_t)(((b * 16 + blockIdx.x) * 8 + wid) * 32) * 32 + lane) * 16;

    const int niter = S / 64;
    for (int it = 0; it < niter; ++it) {
        const int pn = (p + 1 == 3) ? 0 : p + 1;
        if (it + 1 < niter) {
            attn_issue_kv(b, h, it + 1, sb, pn, tid);
            cp_commit();
            cp_wait1();
        } else {
            cp_wait0();
        }

        __syncthreads();   // KV buffer p (and at it=0, Q) ready; single barrier

        if (it == 0) {
            #pragma unroll
            for (int kk = 0; kk < 4; kk++)
                ldsm_x4(qh[kk], sb + (qrow_off + (uint32_t)(kk * 16)) * 2);
        }

        const uint32_t kvb = 9216u + (uint32_t)p * 9216u;
        const uint4* mwp = (const uint4*)(mhp + (size_t)it * 512);

        #pragma unroll
        for (int hf = 0; hf < 2; hf++) {
            // mask frags for this half (load early; consumed after score MMAs)
            const uint4 mA = mwp[hf * 2 + 0];
            const uint4 mB = mwp[hf * 2 + 1];

            // scores for 32 keys: jp = hf*2, hf*2+1
            float sc[4][4] = {};
            #pragma unroll
            for (int jj = 0; jj < 2; jj++) {
                const int jp = hf * 2 + jj;
                const uint32_t krow = (uint32_t)((jp * 16 + (lane & 15)) * 72
                                                 + (lane >> 4) * 8);
                #pragma unroll
                for (int kk = 0; kk < 4; kk++) {
                    uint32_t kh[4];
                    ldsm_x4(kh, sb + (kvb + krow + (uint32_t)(kk * 16)) * 2);
                    mma16816h(sc[jj * 2 + 0], qh[kk], kh[0], kh[2]);
                    mma16816h(sc[jj * 2 + 1], qh[kk], kh[1], kh[3]);
                }
            }

            // ex2 + satfinite pack + fp16 mask multiply
            uint32_t pa[2][4];
            #pragma unroll
            for (int j = 0; j < 4; j++) {
                float e0 = ex2(sc[j][0]);
                float e1 = ex2(sc[j][1]);
                float e2 = ex2(sc[j][2]);
                float e3 = ex2(sc[j][3]);
                pa[j >> 1][(j & 1) * 2 + 0] = h2pack_sat(e0, e1);
                pa[j >> 1][(j & 1) * 2 + 1] = h2pack_sat(e2, e3);
            }
            pa[0][0] = hmul2u(pa[0][0], mA.x);
            pa[0][1] = hmul2u(pa[0][1], mA.y);
            pa[0][2] = hmul2u(pa[0][2], mA.z);
            pa[0][3] = hmul2u(pa[0][3], mA.w);
            pa[1][0] = hmul2u(pa[1][0], mB.x);
            pa[1][1] = hmul2u(pa[1][1], mB.y);
            pa[1][2] = hmul2u(pa[1][2], mB.z);
            pa[1][3] = hmul2u(pa[1][3], mB.w);

            // Zm via ones-column MMA (fp32 accum, consistent with PV's P)
            mma16816h(Oz, pa[0], ONE2, ONE2);
            mma16816h(Oz, pa[1], ONE2, ONE2);

            // PV for key rows hf*32 .. hf*32+31
            #pragma unroll
            for (int j2 = 0; j2 < 2; j2++) {
                const int j2g = hf * 2 + j2;
                const uint32_t vrow = (uint32_t)((j2g * 16 + ((lane >> 3) & 1) * 8
                                                  + (lane & 7)) * 72 + (lane >> 4) * 8);
                #pragma unroll
                for (int ndp = 0; ndp < 4; ndp++) {
                    uint32_t vh[4];
                    ldsm_x4_t(vh, sb + (kvb + 4608u + vrow + (uint32_t)(ndp * 16)) * 2);
                    mma16816h(Oc[ndp * 2 + 0], pa[j2], vh[0], vh[1]);
                    mma16816h(Oc[ndp * 2 + 1], pa[j2], vh[2], vh[3]);
                }
            }
        }
        p = pn;
    }

    // Oz[0] = Zm for row (lane>>2), Oz[2] = row+8 (all cols identical)
    const float inv0 = 1.0f / Oz[0];
    const float inv1 = 1.0f / Oz[2];

    const int row = b * S + q0 + wid * 16 + (lane >> 2);
    #pragma unroll
    for (int nd = 0; nd < 8; nd++) {
        const int col = h * 64 + nd * 8 + (lane & 3) * 2;
        single_store_h(g_ath, (size_t)row * D + col,
                       Oc[nd][0] * inv0, Oc[nd][1] * inv0);
        single_store_h(g_ath, (size_t)(row + 8) * D + col,
                       Oc[nd][2] * inv1, Oc[nd][3] * inv1);
    }
}

// ---------------------------------------------------------------------------
extern "C" void kernel_launch(void* const* d_in, const int* in_sizes, int n_in,
                              void* d_out, int out_size) {
    const float* x         = (const float*)d_in[0];  // [B,S,D]
    const float* Vin       = (const float*)d_in[1];  // [B,S,H,HD]
    const float* Min       = (const float*)d_in[2];  // [B,S,S]
    const float* in_proj_w = (const float*)d_in[3];  // [3D,D]
    const float* in_proj_b = (const float*)d_in[4];  // [3D]
    const float* out_w     = (const float*)d_in[5];  // [D,D]
    const float* out_b     = (const float*)d_in[6];  // [D]
    float* out             = (float*)d_out;          // [B,S,D]

    __half *xh, *w1, *w3, *qk, *ath;
    cudaGetSymbolAddress((void**)&xh,  g_xh);
    cudaGetSymbolAddress((void**)&w1,  g_w1);
    cudaGetSymbolAddress((void**)&w3,  g_w3);
    cudaGetSymbolAddress((void**)&qk,  g_qk);
    cudaGetSymbolAddress((void**)&ath, g_ath);

    cudaFuncSetAttribute(mma_gemm, cudaFuncAttributeMaxDynamicSharedMemorySize, GEMM_SMEM);
    cudaFuncSetAttribute(attn_mma, cudaFuncAttributeMaxDynamicSharedMemorySize, ATTN_SMEM);

    const int Mtot = Bsz * S;  // 4096

    // conversions + fp16 mask expansion
    conv_all<<<(CNT + 255) / 256, 256>>>(x, in_proj_w, out_w, Vin);
    mask_pre<<<262144 / 256, 256>>>(Min);

    // Stage 1: [Q|K] = x @ in_proj_w[0:2D]^T + b -> fp16 single (Q scaled)
    mma_gemm<<<dim3((2 * D) / 128, Mtot / 128), 256, GEMM_SMEM>>>(
        xh, w1, in_proj_b, nullptr, qk, D, 2 * D, 1);

    // Stage 2: masked-renormalized attention -> fp16 single [4096][1024]
    attn_mma<<<dim3(S / 128, H, Bsz), 256, ATTN_SMEM>>>();

    // Stage 3: out = attn @ out_w^T + out_b  (fp32)
    mma_gemm<<<dim3(D / 128, Mtot / 128), 256, GEMM_SMEM>>>(
        ath, w3, out_b, out, nullptr, D, D, 0);
}

// round 13
// speedup vs baseline: 1.0624x; 1.0624x over previous
#include <cuda_runtime.h>
#include <cuda_fp16.h>
#include <cstdint>

#define Bsz 2
#define S   2048
#define D   1024
#define H   16
#define HD  64

// ---------------- scratch (__device__ globals; alloc-free rule) -------------
__device__ __half g_xh[(size_t)Bsz * S * D];        // x fp16 single
__device__ __half g_w1[(size_t)2 * D * D];          // in_proj_w[0:2D] fp16 single
__device__ __half g_w3[(size_t)D * D];              // out_w fp16 single
__device__ __half g_qk[(size_t)Bsz * S * 2 * D];    // Q (scaled 0.125*log2e) | K, fp16 single
__device__ __half g_vh[(size_t)Bsz * S * D];        // V fp16 single
__device__ uint32_t g_mb[262144];                   // packed mask bits
__device__ __half g_ath[(size_t)Bsz * S * D];       // attention out fp16 single

// ---------------- helpers (all plain sm_80+ PTX; no 'a' features) -----------
__device__ __forceinline__ uint32_t smem_u32(const void* p) {
    uint32_t a;
    asm("{ .reg .u64 t; cvta.to.shared.u64 t, %1; cvt.u32.u64 %0, t; }" : "=r"(a) : "l"(p));
    return a;
}
__device__ __forceinline__ void cp16(uint32_t dst, const void* src) {
    asm volatile("cp.async.cg.shared.global [%0], [%1], 16;" :: "r"(dst), "l"(src));
}
__device__ __forceinline__ void cp_commit() {
    asm volatile("cp.async.commit_group;" ::: "memory");
}
__device__ __forceinline__ void cp_wait0() {
    asm volatile("cp.async.wait_group 0;" ::: "memory");
}
__device__ __forceinline__ void cp_wait1() {
    asm volatile("cp.async.wait_group 1;" ::: "memory");
}
__device__ __forceinline__ void ldsm_x4(uint32_t (&r)[4], uint32_t addr) {
    asm volatile("ldmatrix.sync.aligned.m8n8.x4.shared.b16 {%0,%1,%2,%3}, [%4];"
                 : "=r"(r[0]), "=r"(r[1]), "=r"(r[2]), "=r"(r[3]) : "r"(addr));
}
__device__ __forceinline__ void ldsm_x4_t(uint32_t (&r)[4], uint32_t addr) {
    asm volatile("ldmatrix.sync.aligned.m8n8.x4.trans.shared.b16 {%0,%1,%2,%3}, [%4];"
                 : "=r"(r[0]), "=r"(r[1]), "=r"(r[2]), "=r"(r[3]) : "r"(addr));
}
__device__ __forceinline__ void mma16816h(float (&c)[4], const uint32_t (&a)[4],
                                          uint32_t b0, uint32_t b1) {
    asm volatile(
        "mma.sync.aligned.m16n8k16.row.col.f32.f16.f16.f32 "
        "{%0,%1,%2,%3}, {%4,%5,%6,%7}, {%8,%9}, {%0,%1,%2,%3};"
        : "+f"(c[0]), "+f"(c[1]), "+f"(c[2]), "+f"(c[3])
        : "r"(a[0]), "r"(a[1]), "r"(a[2]), "r"(a[3]), "r"(b0), "r"(b1));
}
__device__ __forceinline__ uint32_t h2pack_sat(float lo, float hi) {
    uint32_t r;
    asm("cvt.rn.satfinite.f16x2.f32 %0, %1, %2;" : "=r"(r) : "f"(hi), "f"(lo));
    return r;
}
__device__ __forceinline__ float ex2(float x) {
    float r;
    asm("ex2.approx.f32 %0, %1;" : "=f"(r) : "f"(x));
    return r;
}
__device__ __forceinline__ void single_store_h(__half* Oh, size_t idx,
                                               float v0, float v1) {
    __half2 a; a.x = __float2half_rn(v0); a.y = __float2half_rn(v1);
    *(__half2*)(Oh + idx) = a;
}

// ---------------------------------------------------------------------------
// Fused conversions: x, w1, w3, V -> fp16 single.
// ---------------------------------------------------------------------------
#define CN1 1048576   // x  float4s
#define CN2 524288    // w1
#define CN3 262144    // w3
#define CN4 1048576   // V
#define CNT (CN1 + CN2 + CN3 + CN4)

__global__ __launch_bounds__(256)
void conv_all(const float* __restrict__ x, const float* __restrict__ w1,
              const float* __restrict__ w3, const float* __restrict__ Vin) {
    int i = blockIdx.x * 256 + threadIdx.x;
    if (i >= CNT) return;
    int j = i;
    const float* src;
    __half* o;
    if (j < CN1) { src = x; o = g_xh; }
    else if ((j -= CN1) < CN2) { src = w1; o = g_w1; }
    else if ((j -= CN2) < CN3) { src = w3; o = g_w3; }
    else { j -= CN3; src = Vin; o = g_vh; }
    float4 v = *(const float4*)(src + (size_t)j * 4);
    single_store_h(o, (size_t)j * 4, v.x, v.y);
    single_store_h(o, (size_t)j * 4 + 2, v.z, v.w);
}

// ---------------------------------------------------------------------------
// Mask bit-pack pre-pass (layout matches attention's per-thread frags):
// idx = (((b*128 + qg)*8 + r8)*32 + it)*4 + lg
// ---------------------------------------------------------------------------
__global__ __launch_bounds__(256)
void mask_pre(const float* __restrict__ Min) {
    int idx = blockIdx.x * 256 + threadIdx.x;   // 262144 total
    int lg = idx & 3, it = (idx >> 2) & 31, r8 = (idx >> 7) & 7;
    int qg = (idx >> 10) & 127, b = idx >> 17;
    const float* base = Min + ((size_t)b * S + qg * 16 + r8) * S + it * 64 + lg * 2;
    uint32_t w = 0;
    #pragma unroll
    for (int j = 0; j < 8; j++) {
        float2 a = *(const float2*)(base + j * 8);
        float2 c = *(const float2*)(base + (size_t)8 * S + j * 8);
        if (a.x != 0.f) w |= 1u << (2 * j);
        if (a.y != 0.f) w |= 1u << (2 * j + 1);
        if (c.x != 0.f) w |= 1u << (16 + 2 * j);
        if (c.y != 0.f) w |= 1u << (17 + 2 * j);
    }
    g_mb[idx] = w;
}

// ---------------------------------------------------------------------------
// fp16 single GEMM: C = A[M][K] * B[N][K]^T + bias
// 128x128 tile, BK=32, cp.async double-buffered, 8 warps (2x4).
// mode 0: fp32 out to Cf. mode 1: fp16 single out; Q cols scaled 0.125*log2e.
// ---------------------------------------------------------------------------
#define GEMM_SMEM (2 * 10240 * 2)
#define QSC 0.1803368801111204f   // 0.125 * log2(e)

__device__ __forceinline__ void gemm_issue(
    const __half* A, const __half* Bw,
    int K, int row0, int col0, int chunk, uint32_t dstbase, int tid) {
    #pragma unroll
    for (int j = 0; j < 4; j++) {
        int linear = tid + j * 256;
        int arr = linear >> 9, rem = linear & 511;
        int r = rem >> 2, c = rem & 3;
        const __half* src = arr ? Bw : A;
        int grow = (arr ? col0 : row0) + r;
        cp16(dstbase + (uint32_t)(arr * 5120 + r * 40 + c * 8) * 2,
             src + (size_t)grow * K + chunk * 32 + c * 8);
    }
}

__global__ __launch_bounds__(256, 2)
void mma_gemm(const __half* __restrict__ A, const __half* __restrict__ Bw,
              const float* __restrict__ bias, float* __restrict__ Cf,
              __half* __restrict__ Oh, int K, int N, int mode) {
    extern __shared__ __half smem[];
    const int tid = threadIdx.x;
    const int wid = tid >> 5, lane = tid & 31;
    const int wr = wid >> 2, wc = wid & 3;
    const int row0 = blockIdx.y * 128, col0 = blockIdx.x * 128;
    const uint32_t sb = smem_u32(smem);

    float acc[4][4][4] = {};

    gemm_issue(A, Bw, K, row0, col0, 0, sb, tid);
    cp_commit();

    const int nch = K / 32;
    for (int ch = 0; ch < nch; ++ch) {
        const int p = ch & 1;
        if (ch + 1 < nch) {
            gemm_issue(A, Bw, K, row0, col0, ch + 1, sb + (p ^ 1) * 20480, tid);
            cp_commit();
            cp_wait1();
        } else {
            cp_wait0();
        }
        __syncthreads();

        const uint32_t bufb = sb + p * 20480;
        #pragma unroll
        for (int kk = 0; kk < 2; kk++) {
            const uint32_t koffs = (uint32_t)(kk * 16 + (lane >> 4) * 8);
            uint32_t b0[4], b1[4];
            ldsm_x4(b0, bufb + (5120u + (uint32_t)((wc * 32 + (lane & 15)) * 40) + koffs) * 2);
            ldsm_x4(b1, bufb + (5120u + (uint32_t)((wc * 32 + 16 + (lane & 15)) * 40) + koffs) * 2);
            #pragma unroll
            for (int i = 0; i < 4; i++) {
                uint32_t a4[4];
                ldsm_x4(a4, bufb + ((uint32_t)((wr * 64 + i * 16 + (lane & 15)) * 40) + koffs) * 2);
                mma16816h(acc[i][0], a4, b0[0], b0[2]);
                mma16816h(acc[i][1], a4, b0[1], b0[3]);
                mma16816h(acc[i][2], a4, b1[0], b1[2]);
                mma16816h(acc[i][3], a4, b1[1], b1[3]);
            }
        }
        __syncthreads();
    }

    const float qs = (mode == 1 && col0 < D) ? QSC : 1.0f;
    #pragma unroll
    for (int j = 0; j < 4; j++) {
        const int col = col0 + wc * 32 + j * 8 + (lane & 3) * 2;
        const float b0 = bias[col], b1 = bias[col + 1];
        #pragma unroll
        for (int i = 0; i < 4; i++) {
            const int row = row0 + wr * 64 + i * 16 + (lane >> 2);
            float v0 = (acc[i][j][0] + b0) * qs, v1 = (acc[i][j][1] + b1) * qs;
            float w0 = (acc[i][j][2] + b0) * qs, w1 = (acc[i][j][3] + b1) * qs;
            if (mode == 0) {
                *(float2*)(Cf + (size_t)row * N + col) = make_float2(v0, v1);
                *(float2*)(Cf + (size_t)(row + 8) * N + col) = make_float2(w0, w1);
            } else {
                single_store_h(Oh, (size_t)row * N + col, v0, v1);
                single_store_h(Oh, (size_t)(row + 8) * N + col, w0, w1);
            }
        }
    }
}

// ---------------------------------------------------------------------------
// Attention (fp16 mma, all-single). Per CTA: 128 q rows; 8 warps x 16q x 64k.
// Scores = Q·K (Q pre-scaled 0.125*log2e; e = ex2(s)); Q frags hoisted.
// Mask via 4B bitmask (bit-select, satfinite pack). Zm via ones-column MMA
// (fp32 accum, consistent with PV's exact P frags; no scalar FADDs/shuffles).
// 3-deep KV ring -> ONE barrier per iteration.
// smem halves: Q@0 (9216), 3 KV buffers @9216 stride 9216 (K@0, V@4608).
// ---------------------------------------------------------------------------
#define ATTN_SMEM ((9216 + 3 * 9216) * 2)

__device__ __forceinline__ void attn_issue_kv(int b, int h, int it, uint32_t sb,
                                              int p, int tid) {
    const int k0 = it * 64;
    #pragma unroll
    for (int j = 0; j < 4; j++) {
        int linear = tid + j * 256;
        int arr = linear >> 9, rem = linear & 511;
        int r = rem >> 3, c = rem & 7;
        const __half* src = arr
            ? g_vh + (size_t)(b * S + k0 + r) * 1024 + h * 64 + c * 8
            : g_qk + (size_t)(b * S + k0 + r) * 2048 + D + h * 64 + c * 8;
        cp16(sb + (uint32_t)(9216 + p * 9216 + arr * 4608 + r * 72 + c * 8) * 2, src);
    }
}

__global__ __launch_bounds__(256, 2)
void attn_mma() {
    extern __shared__ __half smh[];
    const int tid = threadIdx.x;
    const int wid = tid >> 5, lane = tid & 31;
    const int b = blockIdx.z, h = blockIdx.y;
    const int q0 = blockIdx.x * 128;
    const uint32_t sb = smem_u32(smh);
    const uint32_t ONE2 = 0x3C003C00u;   // fp16 {1,1}

    // Q -> smem (same commit group as iter-0 K/V)
    #pragma unroll
    for (int j = 0; j < 4; j++) {
        int linear = tid + j * 256;
        int r = linear >> 3, c = linear & 7;
        cp16(sb + (uint32_t)(r * 72 + c * 8) * 2,
             g_qk + (size_t)(b * S + q0 + r) * 2048 + h * 64 + c * 8);
    }
    attn_issue_kv(b, h, 0, sb, 0, tid);
    cp_commit();

    float Oc[8][4] = {};
    float Oz[4] = {};
    uint32_t qh[4][4];   // static Q frags, loaded once at it==0
    int p = 0;

    const uint32_t qrow_off = (uint32_t)((wid * 16 + (lane & 15)) * 72 + (lane >> 4) * 8);
    const uint32_t* mp = g_mb
        + (size_t)((b * 128 + blockIdx.x * 8 + wid) * 8 + (lane >> 2)) * 128 + (lane & 3);

    const int niter = S / 64;
    for (int it = 0; it < niter; ++it) {
        const int pn = (p + 1 == 3) ? 0 : p + 1;
        if (it + 1 < niter) {
            attn_issue_kv(b, h, it + 1, sb, pn, tid);
            cp_commit();
            cp_wait1();
        } else {
            cp_wait0();
        }

        const uint32_t mw = mp[it * 4];   // 4B bitmask, prefetched pre-barrier

        __syncthreads();   // KV buffer p (and at it=0, Q) ready; single barrier

        if (it == 0) {
            #pragma unroll
            for (int kk = 0; kk < 4; kk++)
                ldsm_x4(qh[kk], sb + (qrow_off + (uint32_t)(kk * 16)) * 2);
        }

        const uint32_t kvb = 9216u + (uint32_t)p * 9216u;

        // scores: single term Q x K
        float sc[8][4] = {};
        #pragma unroll
        for (int jp = 0; jp < 4; jp++) {
            const uint32_t krow = (uint32_t)((jp * 16 + (lane & 15)) * 72 + (lane >> 4) * 8);
            #pragma unroll
            for (int kk = 0; kk < 4; kk++) {
                uint32_t kh[4];
                ldsm_x4(kh, sb + (kvb + krow + (uint32_t)(kk * 16)) * 2);
                mma16816h(sc[jp * 2 + 0], qh[kk], kh[0], kh[2]);
                mma16816h(sc[jp * 2 + 1], qh[kk], kh[1], kh[3]);
            }
        }

        // ex2 + bit-mask + satfinite pack P (single fp16) into a-frags
        uint32_t pa[4][4];
        #pragma unroll
        for (int j = 0; j < 8; j++) {
            float e0 = ex2(sc[j][0]);
            float e1 = ex2(sc[j][1]);
            float e2 = ex2(sc[j][2]);
            float e3 = ex2(sc[j][3]);
            float em0 = (mw & (1u << (2 * j)))      ? e0 : 0.0f;
            float em1 = (mw & (1u << (2 * j + 1)))  ? e1 : 0.0f;
            float em2 = (mw & (1u << (16 + 2 * j))) ? e2 : 0.0f;
            float em3 = (mw & (1u << (17 + 2 * j))) ? e3 : 0.0f;
            pa[j >> 1][(j & 1) * 2 + 0] = h2pack_sat(em0, em1);
            pa[j >> 1][(j & 1) * 2 + 1] = h2pack_sat(em2, em3);
        }

        // Zm via ones-column MMA (replaces 32 FADDs + final shuffle reduce)
        mma16816h(Oz, pa[0], ONE2, ONE2);
        mma16816h(Oz, pa[1], ONE2, ONE2);
        mma16816h(Oz, pa[2], ONE2, ONE2);
        mma16816h(Oz, pa[3], ONE2, ONE2);

        // PV: single term
        #pragma unroll
        for (int j2 = 0; j2 < 4; j2++) {
            const uint32_t vrow = (uint32_t)((j2 * 16 + ((lane >> 3) & 1) * 8 + (lane & 7)) * 72
                                             + (lane >> 4) * 8);
            #pragma unroll
            for (int ndp = 0; ndp < 4; ndp++) {
                uint32_t vh[4];
                ldsm_x4_t(vh, sb + (kvb + 4608u + vrow + (uint32_t)(ndp * 16)) * 2);
                mma16816h(Oc[ndp * 2 + 0], pa[j2], vh[0], vh[1]);
                mma16816h(Oc[ndp * 2 + 1], pa[j2], vh[2], vh[3]);
            }
        }
        p = pn;
    }

    // Oz[0] = Zm for row (lane>>2), Oz[2] = row+8 (all accumulator cols equal)
    const float inv0 = 1.0f / Oz[0];
    const float inv1 = 1.0f / Oz[2];

    const int row = b * S + q0 + wid * 16 + (lane >> 2);
    #pragma unroll
    for (int nd = 0; nd < 8; nd++) {
        const int col = h * 64 + nd * 8 + (lane & 3) * 2;
        single_store_h(g_ath, (size_t)row * D + col,
                       Oc[nd][0] * inv0, Oc[nd][1] * inv0);
        single_store_h(g_ath, (size_t)(row + 8) * D + col,
                       Oc[nd][2] * inv1, Oc[nd][3] * inv1);
    }
}

// ---------------------------------------------------------------------------
extern "C" void kernel_launch(void* const* d_in, const int* in_sizes, int n_in,
                              void* d_out, int out_size) {
    const float* x         = (const float*)d_in[0];  // [B,S,D]
    const float* Vin       = (const float*)d_in[1];  // [B,S,H,HD]
    const float* Min       = (const float*)d_in[2];  // [B,S,S]
    const float* in_proj_w = (const float*)d_in[3];  // [3D,D]
    const float* in_proj_b = (const float*)d_in[4];  // [3D]
    const float* out_w     = (const float*)d_in[5];  // [D,D]
    const float* out_b     = (const float*)d_in[6];  // [D]
    float* out             = (float*)d_out;          // [B,S,D]

    __half *xh, *w1, *w3, *qk, *ath;
    cudaGetSymbolAddress((void**)&xh,  g_xh);
    cudaGetSymbolAddress((void**)&w1,  g_w1);
    cudaGetSymbolAddress((void**)&w3,  g_w3);
    cudaGetSymbolAddress((void**)&qk,  g_qk);
    cudaGetSymbolAddress((void**)&ath, g_ath);

    cudaFuncSetAttribute(mma_gemm, cudaFuncAttributeMaxDynamicSharedMemorySize, GEMM_SMEM);
    cudaFuncSetAttribute(attn_mma, cudaFuncAttributeMaxDynamicSharedMemorySize, ATTN_SMEM);

    const int Mtot = Bsz * S;  // 4096

    // conversions + mask bit-pack
    conv_all<<<(CNT + 255) / 256, 256>>>(x, in_proj_w, out_w, Vin);
    mask_pre<<<262144 / 256, 256>>>(Min);

    // Stage 1: [Q|K] = x @ in_proj_w[0:2D]^T + b -> fp16 single (Q scaled)
    mma_gemm<<<dim3((2 * D) / 128, Mtot / 128), 256, GEMM_SMEM>>>(
        xh, w1, in_proj_b, nullptr, qk, D, 2 * D, 1);

    // Stage 2: masked-renormalized attention -> fp16 single [4096][1024]
    attn_mma<<<dim3(S / 128, H, Bsz), 256, ATTN_SMEM>>>();

    // Stage 3: out = attn @ out_w^T + out_b  (fp32)
    mma_gemm<<<dim3(D / 128, Mtot / 128), 256, GEMM_SMEM>>>(
        ath, w3, out_b, out, nullptr, D, D, 0);
}

// round 14
// speedup vs baseline: 1.0948x; 1.0306x over previous
#include <cuda_runtime.h>
#include <cuda_fp16.h>
#include <cstdint>

#define Bsz 2
#define S   2048
#define D   1024
#define H   16
#define HD  64

// ---------------- scratch (__device__ globals; alloc-free rule) -------------
__device__ __half g_xh[(size_t)Bsz * S * D];        // x fp16 single
__device__ __half g_w1[(size_t)2 * D * D];          // in_proj_w[0:2D] fp16 single
__device__ __half g_w3[(size_t)D * D];              // out_w fp16 single
__device__ __half g_qk[(size_t)Bsz * S * 2 * D];    // Q (scaled 0.125*log2e) | K, fp16 single
__device__ __half g_vh[(size_t)Bsz * S * D];        // V fp16 single
__device__ uint32_t g_mb[262144];                   // packed mask bits
__device__ __half g_ath[(size_t)Bsz * S * D];       // attention out fp16 single

// ---------------- helpers (all plain sm_80+ PTX; no 'a' features) -----------
__device__ __forceinline__ uint32_t smem_u32(const void* p) {
    uint32_t a;
    asm("{ .reg .u64 t; cvta.to.shared.u64 t, %1; cvt.u32.u64 %0, t; }" : "=r"(a) : "l"(p));
    return a;
}
__device__ __forceinline__ void cp16(uint32_t dst, const void* src) {
    asm volatile("cp.async.cg.shared.global [%0], [%1], 16;" :: "r"(dst), "l"(src));
}
__device__ __forceinline__ void cp_commit() {
    asm volatile("cp.async.commit_group;" ::: "memory");
}
__device__ __forceinline__ void cp_wait0() {
    asm volatile("cp.async.wait_group 0;" ::: "memory");
}
__device__ __forceinline__ void cp_wait1() {
    asm volatile("cp.async.wait_group 1;" ::: "memory");
}
__device__ __forceinline__ void ldsm_x4(uint32_t (&r)[4], uint32_t addr) {
    asm volatile("ldmatrix.sync.aligned.m8n8.x4.shared.b16 {%0,%1,%2,%3}, [%4];"
                 : "=r"(r[0]), "=r"(r[1]), "=r"(r[2]), "=r"(r[3]) : "r"(addr));
}
__device__ __forceinline__ void ldsm_x4_t(uint32_t (&r)[4], uint32_t addr) {
    asm volatile("ldmatrix.sync.aligned.m8n8.x4.trans.shared.b16 {%0,%1,%2,%3}, [%4];"
                 : "=r"(r[0]), "=r"(r[1]), "=r"(r[2]), "=r"(r[3]) : "r"(addr));
}
__device__ __forceinline__ void mma16816h(float (&c)[4], const uint32_t (&a)[4],
                                          uint32_t b0, uint32_t b1) {
    asm volatile(
        "mma.sync.aligned.m16n8k16.row.col.f32.f16.f16.f32 "
        "{%0,%1,%2,%3}, {%4,%5,%6,%7}, {%8,%9}, {%0,%1,%2,%3};"
        : "+f"(c[0]), "+f"(c[1]), "+f"(c[2]), "+f"(c[3])
        : "r"(a[0]), "r"(a[1]), "r"(a[2]), "r"(a[3]), "r"(b0), "r"(b1));
}
__device__ __forceinline__ uint32_t h2pack_sat(float lo, float hi) {
    uint32_t r;
    asm("cvt.rn.satfinite.f16x2.f32 %0, %1, %2;" : "=r"(r) : "f"(hi), "f"(lo));
    return r;
}
__device__ __forceinline__ float ex2(float x) {
    float r;
    asm("ex2.approx.f32 %0, %1;" : "=f"(r) : "f"(x));
    return r;
}
__device__ __forceinline__ void single_store_h(__half* Oh, size_t idx,
                                               float v0, float v1) {
    __half2 a; a.x = __float2half_rn(v0); a.y = __float2half_rn(v1);
    *(__half2*)(Oh + idx) = a;
}

// ---------------------------------------------------------------------------
// Fused pre-pass: x, w1, w3, V -> fp16 single; then mask bit-pack.
// ---------------------------------------------------------------------------
#define CN1 1048576   // x  float4s
#define CN2 524288    // w1
#define CN3 262144    // w3
#define CN4 1048576   // V
#define CNT (CN1 + CN2 + CN3 + CN4)
#define CNM 262144    // mask words
#define CNTOT (CNT + CNM)

__global__ __launch_bounds__(256)
void conv_all(const float* __restrict__ x, const float* __restrict__ w1,
              const float* __restrict__ w3, const float* __restrict__ Vin,
              const float* __restrict__ Min) {
    int i = blockIdx.x * 256 + threadIdx.x;
    if (i >= CNTOT) return;
    if (i >= CNT) {
        // mask bit-pack: idx = (((b*128+qg)*8+r8)*32+it)*4+lg
        int idx = i - CNT;
        int lg = idx & 3, it = (idx >> 2) & 31, r8 = (idx >> 7) & 7;
        int qg = (idx >> 10) & 127, b = idx >> 17;
        const float* base = Min + ((size_t)b * S + qg * 16 + r8) * S + it * 64 + lg * 2;
        uint32_t w = 0;
        #pragma unroll
        for (int j = 0; j < 8; j++) {
            float2 a = *(const float2*)(base + j * 8);
            float2 c = *(const float2*)(base + (size_t)8 * S + j * 8);
            if (a.x != 0.f) w |= 1u << (2 * j);
            if (a.y != 0.f) w |= 1u << (2 * j + 1);
            if (c.x != 0.f) w |= 1u << (16 + 2 * j);
            if (c.y != 0.f) w |= 1u << (17 + 2 * j);
        }
        g_mb[idx] = w;
        return;
    }
    int j = i;
    const float* src;
    __half* o;
    if (j < CN1) { src = x; o = g_xh; }
    else if ((j -= CN1) < CN2) { src = w1; o = g_w1; }
    else if ((j -= CN2) < CN3) { src = w3; o = g_w3; }
    else { j -= CN3; src = Vin; o = g_vh; }
    float4 v = *(const float4*)(src + (size_t)j * 4);
    single_store_h(o, (size_t)j * 4, v.x, v.y);
    single_store_h(o, (size_t)j * 4 + 2, v.z, v.w);
}

// ---------------------------------------------------------------------------
// fp16 single GEMM: C = A[M][K] * B[N][K]^T + bias
// 128x128 tile, BK=32, cp.async double-buffered, 8 warps (2x4).
// mode 0: fp32 out to Cf. mode 1: fp16 single out; Q cols scaled 0.125*log2e.
// ---------------------------------------------------------------------------
#define GEMM_SMEM (2 * 10240 * 2)
#define QSC 0.1803368801111204f   // 0.125 * log2(e)

__device__ __forceinline__ void gemm_issue(
    const __half* A, const __half* Bw,
    int K, int row0, int col0, int chunk, uint32_t dstbase, int tid) {
    #pragma unroll
    for (int j = 0; j < 4; j++) {
        int linear = tid + j * 256;
        int arr = linear >> 9, rem = linear & 511;
        int r = rem >> 2, c = rem & 3;
        const __half* src = arr ? Bw : A;
        int grow = (arr ? col0 : row0) + r;
        cp16(dstbase + (uint32_t)(arr * 5120 + r * 40 + c * 8) * 2,
             src + (size_t)grow * K + chunk * 32 + c * 8);
    }
}

__global__ __launch_bounds__(256, 2)
void mma_gemm(const __half* __restrict__ A, const __half* __restrict__ Bw,
              const float* __restrict__ bias, float* __restrict__ Cf,
              __half* __restrict__ Oh, int K, int N, int mode) {
    extern __shared__ __half smem[];
    const int tid = threadIdx.x;
    const int wid = tid >> 5, lane = tid & 31;
    const int wr = wid >> 2, wc = wid & 3;
    const int row0 = blockIdx.y * 128, col0 = blockIdx.x * 128;
    const uint32_t sb = smem_u32(smem);

    float acc[4][4][4] = {};

    gemm_issue(A, Bw, K, row0, col0, 0, sb, tid);
    cp_commit();

    const int nch = K / 32;
    for (int ch = 0; ch < nch; ++ch) {
        const int p = ch & 1;
        if (ch + 1 < nch) {
            gemm_issue(A, Bw, K, row0, col0, ch + 1, sb + (p ^ 1) * 20480, tid);
            cp_commit();
            cp_wait1();
        } else {
            cp_wait0();
        }
        __syncthreads();

        const uint32_t bufb = sb + p * 20480;
        #pragma unroll
        for (int kk = 0; kk < 2; kk++) {
            const uint32_t koffs = (uint32_t)(kk * 16 + (lane >> 4) * 8);
            uint32_t b0[4], b1[4];
            ldsm_x4(b0, bufb + (5120u + (uint32_t)((wc * 32 + (lane & 15)) * 40) + koffs) * 2);
            ldsm_x4(b1, bufb + (5120u + (uint32_t)((wc * 32 + 16 + (lane & 15)) * 40) + koffs) * 2);
            #pragma unroll
            for (int i = 0; i < 4; i++) {
                uint32_t a4[4];
                ldsm_x4(a4, bufb + ((uint32_t)((wr * 64 + i * 16 + (lane & 15)) * 40) + koffs) * 2);
                mma16816h(acc[i][0], a4, b0[0], b0[2]);
                mma16816h(acc[i][1], a4, b0[1], b0[3]);
                mma16816h(acc[i][2], a4, b1[0], b1[2]);
                mma16816h(acc[i][3], a4, b1[1], b1[3]);
            }
        }
        __syncthreads();
    }

    const float qs = (mode == 1 && col0 < D) ? QSC : 1.0f;
    #pragma unroll
    for (int j = 0; j < 4; j++) {
        const int col = col0 + wc * 32 + j * 8 + (lane & 3) * 2;
        const float b0 = bias[col], b1 = bias[col + 1];
        #pragma unroll
        for (int i = 0; i < 4; i++) {
            const int row = row0 + wr * 64 + i * 16 + (lane >> 2);
            float v0 = (acc[i][j][0] + b0) * qs, v1 = (acc[i][j][1] + b1) * qs;
            float w0 = (acc[i][j][2] + b0) * qs, w1 = (acc[i][j][3] + b1) * qs;
            if (mode == 0) {
                *(float2*)(Cf + (size_t)row * N + col) = make_float2(v0, v1);
                *(float2*)(Cf + (size_t)(row + 8) * N + col) = make_float2(w0, w1);
            } else {
                single_store_h(Oh, (size_t)row * N + col, v0, v1);
                single_store_h(Oh, (size_t)(row + 8) * N + col, w0, w1);
            }
        }
    }
}

// ---------------------------------------------------------------------------
// Attention (fp16 mma, all-single). Per CTA: 128 q rows; 8 warps x 16q x 64k,
// processed as two independent 32-key halves so hf1's score chain (HMMA+ldsm)
// can overlap hf0's ex2 (MUFU) in the scheduler. Bitmask masking, scalar Zm.
// Scores = Q·K (Q pre-scaled 0.125*log2e; e = ex2(s)); Q frags hoisted.
// 3-deep KV ring -> ONE barrier per iteration.
// smem halves: Q@0 (9216), 3 KV buffers @9216 stride 9216 (K@0, V@4608).
// ---------------------------------------------------------------------------
#define ATTN_SMEM ((9216 + 3 * 9216) * 2)

__device__ __forceinline__ void attn_issue_kv(int b, int h, int it, uint32_t sb,
                                              int p, int tid) {
    const int k0 = it * 64;
    #pragma unroll
    for (int j = 0; j < 4; j++) {
        int linear = tid + j * 256;
        int arr = linear >> 9, rem = linear & 511;
        int r = rem >> 3, c = rem & 7;
        const __half* src = arr
            ? g_vh + (size_t)(b * S + k0 + r) * 1024 + h * 64 + c * 8
            : g_qk + (size_t)(b * S + k0 + r) * 2048 + D + h * 64 + c * 8;
        cp16(sb + (uint32_t)(9216 + p * 9216 + arr * 4608 + r * 72 + c * 8) * 2, src);
    }
}

__global__ __launch_bounds__(256, 2)
void attn_mma() {
    extern __shared__ __half smh[];
    const int tid = threadIdx.x;
    const int wid = tid >> 5, lane = tid & 31;
    const int b = blockIdx.z, h = blockIdx.y;
    const int q0 = blockIdx.x * 128;
    const uint32_t sb = smem_u32(smh);

    // Q -> smem (same commit group as iter-0 K/V)
    #pragma unroll
    for (int j = 0; j < 4; j++) {
        int linear = tid + j * 256;
        int r = linear >> 3, c = linear & 7;
        cp16(sb + (uint32_t)(r * 72 + c * 8) * 2,
             g_qk + (size_t)(b * S + q0 + r) * 2048 + h * 64 + c * 8);
    }
    attn_issue_kv(b, h, 0, sb, 0, tid);
    cp_commit();

    float Oc[8][4] = {};
    float zm0 = 0.f, zm1 = 0.f;
    uint32_t qh[4][4];   // static Q frags, loaded once at it==0
    int p = 0;

    const uint32_t qrow_off = (uint32_t)((wid * 16 + (lane & 15)) * 72 + (lane >> 4) * 8);
    const uint32_t* mp = g_mb
        + (size_t)((b * 128 + blockIdx.x * 8 + wid) * 8 + (lane >> 2)) * 128 + (lane & 3);

    const int niter = S / 64;
    for (int it = 0; it < niter; ++it) {
        const int pn = (p + 1 == 3) ? 0 : p + 1;
        if (it + 1 < niter) {
            attn_issue_kv(b, h, it + 1, sb, pn, tid);
            cp_commit();
            cp_wait1();
        } else {
            cp_wait0();
        }

        const uint32_t mw = mp[it * 4];   // 4B bitmask, prefetched pre-barrier

        __syncthreads();   // KV buffer p (and at it=0, Q) ready; single barrier

        if (it == 0) {
            #pragma unroll
            for (int kk = 0; kk < 4; kk++)
                ldsm_x4(qh[kk], sb + (qrow_off + (uint32_t)(kk * 16)) * 2);
        }

        const uint32_t kvb = 9216u + (uint32_t)p * 9216u;

        // two independent 32-key halves -> MUFU of one overlaps HMMA of other
        #pragma unroll
        for (int hf = 0; hf < 2; hf++) {
            // scores for keys [hf*32, hf*32+32)
            float sc[4][4] = {};
            #pragma unroll
            for (int jj = 0; jj < 2; jj++) {
                const int jp = hf * 2 + jj;
                const uint32_t krow = (uint32_t)((jp * 16 + (lane & 15)) * 72
                                                 + (lane >> 4) * 8);
                #pragma unroll
                for (int kk = 0; kk < 4; kk++) {
                    uint32_t kh[4];
                    ldsm_x4(kh, sb + (kvb + krow + (uint32_t)(kk * 16)) * 2);
                    mma16816h(sc[jj * 2 + 0], qh[kk], kh[0], kh[2]);
                    mma16816h(sc[jj * 2 + 1], qh[kk], kh[1], kh[3]);
                }
            }

            // ex2 + bit-mask + Zm + pack P into a-frags
            uint32_t pa[2][4];
            #pragma unroll
            for (int j = 0; j < 4; j++) {
                const int jg = hf * 4 + j;
                float e0 = ex2(sc[j][0]);
                float e1 = ex2(sc[j][1]);
                float e2 = ex2(sc[j][2]);
                float e3 = ex2(sc[j][3]);
                float em0 = (mw & (1u << (2 * jg)))      ? e0 : 0.0f;
                float em1 = (mw & (1u << (2 * jg + 1)))  ? e1 : 0.0f;
                float em2 = (mw & (1u << (16 + 2 * jg))) ? e2 : 0.0f;
                float em3 = (mw & (1u << (17 + 2 * jg))) ? e3 : 0.0f;
                zm0 += em0 + em1; zm1 += em2 + em3;
                pa[j >> 1][(j & 1) * 2 + 0] = h2pack_sat(em0, em1);
                pa[j >> 1][(j & 1) * 2 + 1] = h2pack_sat(em2, em3);
            }

            // PV for key rows [hf*32, hf*32+32)
            #pragma unroll
            for (int j2 = 0; j2 < 2; j2++) {
                const int j2g = hf * 2 + j2;
                const uint32_t vrow = (uint32_t)((j2g * 16 + ((lane >> 3) & 1) * 8
                                                  + (lane & 7)) * 72 + (lane >> 4) * 8);
                #pragma unroll
                for (int ndp = 0; ndp < 4; ndp++) {
                    uint32_t vh[4];
                    ldsm_x4_t(vh, sb + (kvb + 4608u + vrow + (uint32_t)(ndp * 16)) * 2);
                    mma16816h(Oc[ndp * 2 + 0], pa[j2], vh[0], vh[1]);
                    mma16816h(Oc[ndp * 2 + 1], pa[j2], vh[2], vh[3]);
                }
            }
        }
        p = pn;
    }

    // quad reduce Zm (lanes sharing lane>>2 hold the same rows)
    #pragma unroll
    for (int off = 1; off < 4; off <<= 1) {
        zm0 += __shfl_xor_sync(0xffffffffu, zm0, off);
        zm1 += __shfl_xor_sync(0xffffffffu, zm1, off);
    }
    const float inv0 = 1.0f / zm0;
    const float inv1 = 1.0f / zm1;

    const int row = b * S + q0 + wid * 16 + (lane >> 2);
    #pragma unroll
    for (int nd = 0; nd < 8; nd++) {
        const int col = h * 64 + nd * 8 + (lane & 3) * 2;
        single_store_h(g_ath, (size_t)row * D + col,
                       Oc[nd][0] * inv0, Oc[nd][1] * inv0);
        single_store_h(g_ath, (size_t)(row + 8) * D + col,
                       Oc[nd][2] * inv1, Oc[nd][3] * inv1);
    }
}

// ---------------------------------------------------------------------------
extern "C" void kernel_launch(void* const* d_in, const int* in_sizes, int n_in,
                              void* d_out, int out_size) {
    const float* x         = (const float*)d_in[0];  // [B,S,D]
    const float* Vin       = (const float*)d_in[1];  // [B,S,H,HD]
    const float* Min       = (const float*)d_in[2];  // [B,S,S]
    const float* in_proj_w = (const float*)d_in[3];  // [3D,D]
    const float* in_proj_b = (const float*)d_in[4];  // [3D]
    const float* out_w     = (const float*)d_in[5];  // [D,D]
    const float* out_b     = (const float*)d_in[6];  // [D]
    float* out             = (float*)d_out;          // [B,S,D]

    __half *xh, *w1, *w3, *qk, *ath;
    cudaGetSymbolAddress((void**)&xh,  g_xh);
    cudaGetSymbolAddress((void**)&w1,  g_w1);
    cudaGetSymbolAddress((void**)&w3,  g_w3);
    cudaGetSymbolAddress((void**)&qk,  g_qk);
    cudaGetSymbolAddress((void**)&ath, g_ath);

    cudaFuncSetAttribute(mma_gemm, cudaFuncAttributeMaxDynamicSharedMemorySize, GEMM_SMEM);
    cudaFuncSetAttribute(attn_mma, cudaFuncAttributeMaxDynamicSharedMemorySize, ATTN_SMEM);

    const int Mtot = Bsz * S;  // 4096

    // fused conversions + mask bit-pack (one launch)
    conv_all<<<(CNTOT + 255) / 256, 256>>>(x, in_proj_w, out_w, Vin, Min);

    // Stage 1: [Q|K] = x @ in_proj_w[0:2D]^T + b -> fp16 single (Q scaled)
    mma_gemm<<<dim3((2 * D) / 128, Mtot / 128), 256, GEMM_SMEM>>>(
        xh, w1, in_proj_b, nullptr, qk, D, 2 * D, 1);

    // Stage 2: masked-renormalized attention -> fp16 single [4096][1024]
    attn_mma<<<dim3(S / 128, H, Bsz), 256, ATTN_SMEM>>>();

    // Stage 3: out = attn @ out_w^T + out_b  (fp32)
    mma_gemm<<<dim3(D / 128, Mtot / 128), 256, GEMM_SMEM>>>(
        ath, w3, out_b, out, nullptr, D, D, 0);
}

// round 15
// speedup vs baseline: 1.1027x; 1.0072x over previous
#include <cuda_runtime.h>
#include <cuda_fp16.h>
#include <cstdint>

#define Bsz 2
#define S   2048
#define D   1024
#define H   16
#define HD  64

// ---------------- scratch (__device__ globals; alloc-free rule) -------------
__device__ __half g_xh[(size_t)Bsz * S * D];        // x fp16 single
__device__ __half g_w1[(size_t)2 * D * D];          // in_proj_w[0:2D] fp16 single
__device__ __half g_w3[(size_t)D * D];              // out_w fp16 single
__device__ __half g_qk[(size_t)Bsz * S * 2 * D];    // Q (scaled 0.125*log2e) | K, fp16 single
__device__ __half g_vh[(size_t)Bsz * S * D];        // V fp16 single
__device__ uint32_t g_mb[262144];                   // packed mask bits
__device__ __half g_ath[(size_t)Bsz * S * D];       // attention out fp16 single

// ---------------- helpers (all plain sm_80+ PTX; no 'a' features) -----------
__device__ __forceinline__ uint32_t smem_u32(const void* p) {
    uint32_t a;
    asm("{ .reg .u64 t; cvta.to.shared.u64 t, %1; cvt.u32.u64 %0, t; }" : "=r"(a) : "l"(p));
    return a;
}
__device__ __forceinline__ void cp16(uint32_t dst, const void* src) {
    asm volatile("cp.async.cg.shared.global [%0], [%1], 16;" :: "r"(dst), "l"(src));
}
__device__ __forceinline__ void cp_commit() {
    asm volatile("cp.async.commit_group;" ::: "memory");
}
__device__ __forceinline__ void cp_wait0() {
    asm volatile("cp.async.wait_group 0;" ::: "memory");
}
__device__ __forceinline__ void cp_wait1() {
    asm volatile("cp.async.wait_group 1;" ::: "memory");
}
__device__ __forceinline__ void cp_wait2() {
    asm volatile("cp.async.wait_group 2;" ::: "memory");
}
__device__ __forceinline__ void ldsm_x4(uint32_t (&r)[4], uint32_t addr) {
    asm volatile("ldmatrix.sync.aligned.m8n8.x4.shared.b16 {%0,%1,%2,%3}, [%4];"
                 : "=r"(r[0]), "=r"(r[1]), "=r"(r[2]), "=r"(r[3]) : "r"(addr));
}
__device__ __forceinline__ void ldsm_x4_t(uint32_t (&r)[4], uint32_t addr) {
    asm volatile("ldmatrix.sync.aligned.m8n8.x4.trans.shared.b16 {%0,%1,%2,%3}, [%4];"
                 : "=r"(r[0]), "=r"(r[1]), "=r"(r[2]), "=r"(r[3]) : "r"(addr));
}
__device__ __forceinline__ void mma16816h(float (&c)[4], const uint32_t (&a)[4],
                                          uint32_t b0, uint32_t b1) {
    asm volatile(
        "mma.sync.aligned.m16n8k16.row.col.f32.f16.f16.f32 "
        "{%0,%1,%2,%3}, {%4,%5,%6,%7}, {%8,%9}, {%0,%1,%2,%3};"
        : "+f"(c[0]), "+f"(c[1]), "+f"(c[2]), "+f"(c[3])
        : "r"(a[0]), "r"(a[1]), "r"(a[2]), "r"(a[3]), "r"(b0), "r"(b1));
}
__device__ __forceinline__ uint32_t h2pack_sat(float lo, float hi) {
    uint32_t r;
    asm("cvt.rn.satfinite.f16x2.f32 %0, %1, %2;" : "=r"(r) : "f"(hi), "f"(lo));
    return r;
}
__device__ __forceinline__ float ex2(float x) {
    float r;
    asm("ex2.approx.f32 %0, %1;" : "=f"(r) : "f"(x));
    return r;
}
__device__ __forceinline__ void single_store_h(__half* Oh, size_t idx,
                                               float v0, float v1) {
    __half2 a; a.x = __float2half_rn(v0); a.y = __float2half_rn(v1);
    *(__half2*)(Oh + idx) = a;
}

// ---------------------------------------------------------------------------
// Fused pre-pass: x, w1, w3, V -> fp16 single; then mask bit-pack.
// ---------------------------------------------------------------------------
#define CN1 1048576   // x  float4s
#define CN2 524288    // w1
#define CN3 262144    // w3
#define CN4 1048576   // V
#define CNT (CN1 + CN2 + CN3 + CN4)
#define CNM 262144    // mask words
#define CNTOT (CNT + CNM)

__global__ __launch_bounds__(256)
void conv_all(const float* __restrict__ x, const float* __restrict__ w1,
              const float* __restrict__ w3, const float* __restrict__ Vin,
              const float* __restrict__ Min) {
    int i = blockIdx.x * 256 + threadIdx.x;
    if (i >= CNTOT) return;
    if (i >= CNT) {
        // mask bit-pack: idx = (((b*128+qg)*8+r8)*32+it)*4+lg
        int idx = i - CNT;
        int lg = idx & 3, it = (idx >> 2) & 31, r8 = (idx >> 7) & 7;
        int qg = (idx >> 10) & 127, b = idx >> 17;
        const float* base = Min + ((size_t)b * S + qg * 16 + r8) * S + it * 64 + lg * 2;
        uint32_t w = 0;
        #pragma unroll
        for (int j = 0; j < 8; j++) {
            float2 a = *(const float2*)(base + j * 8);
            float2 c = *(const float2*)(base + (size_t)8 * S + j * 8);
            if (a.x != 0.f) w |= 1u << (2 * j);
            if (a.y != 0.f) w |= 1u << (2 * j + 1);
            if (c.x != 0.f) w |= 1u << (16 + 2 * j);
            if (c.y != 0.f) w |= 1u << (17 + 2 * j);
        }
        g_mb[idx] = w;
        return;
    }
    int j = i;
    const float* src;
    __half* o;
    if (j < CN1) { src = x; o = g_xh; }
    else if ((j -= CN1) < CN2) { src = w1; o = g_w1; }
    else if ((j -= CN2) < CN3) { src = w3; o = g_w3; }
    else { j -= CN3; src = Vin; o = g_vh; }
    float4 v = *(const float4*)(src + (size_t)j * 4);
    single_store_h(o, (size_t)j * 4, v.x, v.y);
    single_store_h(o, (size_t)j * 4 + 2, v.z, v.w);
}

// ---------------------------------------------------------------------------
// fp16 single GEMM: C = A[M][K] * B[N][K]^T + bias
// 128x128 tile, BK=32, cp.async 4-stage pipeline (issue-ahead-3), 8 warps.
// ONE barrier per chunk; issue placed after the barrier so a fast warp can
// never overwrite a buffer a slow warp still reads (ring-safety argument).
// mode 0: fp32 out to Cf. mode 1: fp16 single out; Q cols scaled 0.125*log2e.
// ---------------------------------------------------------------------------
#define GEMM_SMEM (4 * 10240 * 2)   // 4 buffers x 20480 bytes
#define QSC 0.1803368801111204f     // 0.125 * log2(e)

__device__ __forceinline__ void gemm_issue(
    const __half* A, const __half* Bw,
    int K, int row0, int col0, int chunk, uint32_t dstbase, int tid) {
    #pragma unroll
    for (int j = 0; j < 4; j++) {
        int linear = tid + j * 256;
        int arr = linear >> 9, rem = linear & 511;
        int r = rem >> 2, c = rem & 3;
        const __half* src = arr ? Bw : A;
        int grow = (arr ? col0 : row0) + r;
        cp16(dstbase + (uint32_t)(arr * 5120 + r * 40 + c * 8) * 2,
             src + (size_t)grow * K + chunk * 32 + c * 8);
    }
}

__global__ __launch_bounds__(256, 2)
void mma_gemm(const __half* __restrict__ A, const __half* __restrict__ Bw,
              const float* __restrict__ bias, float* __restrict__ Cf,
              __half* __restrict__ Oh, int K, int N, int mode) {
    extern __shared__ __half smem[];
    const int tid = threadIdx.x;
    const int wid = tid >> 5, lane = tid & 31;
    const int wr = wid >> 2, wc = wid & 3;
    const int row0 = blockIdx.y * 128, col0 = blockIdx.x * 128;
    const uint32_t sb = smem_u32(smem);

    float acc[4][4][4] = {};

    const int nch = K / 32;
    // prologue: fill 3 of 4 buffers
    gemm_issue(A, Bw, K, row0, col0, 0, sb, tid);               cp_commit();
    gemm_issue(A, Bw, K, row0, col0, 1, sb + 20480u, tid);      cp_commit();
    gemm_issue(A, Bw, K, row0, col0, 2, sb + 40960u, tid);      cp_commit();

    for (int ch = 0; ch < nch; ++ch) {
        // wait until chunk ch's group is complete (pending <= issued-ch-1)
        if (ch < nch - 2)       cp_wait2();
        else if (ch == nch - 2) cp_wait1();
        else                    cp_wait0();
        __syncthreads();   // publishes buffer ch; also fences prev compute on (ch+3)&3

        if (ch + 3 < nch) {
            gemm_issue(A, Bw, K, row0, col0, ch + 3,
                       sb + (uint32_t)((ch + 3) & 3) * 20480u, tid);
            cp_commit();
        }

        const uint32_t bufb = sb + (uint32_t)(ch & 3) * 20480u;
        #pragma unroll
        for (int kk = 0; kk < 2; kk++) {
            const uint32_t koffs = (uint32_t)(kk * 16 + (lane >> 4) * 8);
            uint32_t b0[4], b1[4];
            ldsm_x4(b0, bufb + (5120u + (uint32_t)((wc * 32 + (lane & 15)) * 40) + koffs) * 2);
            ldsm_x4(b1, bufb + (5120u + (uint32_t)((wc * 32 + 16 + (lane & 15)) * 40) + koffs) * 2);
            #pragma unroll
            for (int i = 0; i < 4; i++) {
                uint32_t a4[4];
                ldsm_x4(a4, bufb + ((uint32_t)((wr * 64 + i * 16 + (lane & 15)) * 40) + koffs) * 2);
                mma16816h(acc[i][0], a4, b0[0], b0[2]);
                mma16816h(acc[i][1], a4, b0[1], b0[3]);
                mma16816h(acc[i][2], a4, b1[0], b1[2]);
                mma16816h(acc[i][3], a4, b1[1], b1[3]);
            }
        }
    }

    const float qs = (mode == 1 && col0 < D) ? QSC : 1.0f;
    #pragma unroll
    for (int j = 0; j < 4; j++) {
        const int col = col0 + wc * 32 + j * 8 + (lane & 3) * 2;
        const float b0 = bias[col], b1 = bias[col + 1];
        #pragma unroll
        for (int i = 0; i < 4; i++) {
            const int row = row0 + wr * 64 + i * 16 + (lane >> 2);
            float v0 = (acc[i][j][0] + b0) * qs, v1 = (acc[i][j][1] + b1) * qs;
            float w0 = (acc[i][j][2] + b0) * qs, w1 = (acc[i][j][3] + b1) * qs;
            if (mode == 0) {
                *(float2*)(Cf + (size_t)row * N + col) = make_float2(v0, v1);
                *(float2*)(Cf + (size_t)(row + 8) * N + col) = make_float2(w0, w1);
            } else {
                single_store_h(Oh, (size_t)row * N + col, v0, v1);
                single_store_h(Oh, (size_t)(row + 8) * N + col, w0, w1);
            }
        }
    }
}

// ---------------------------------------------------------------------------
// Attention (fp16 mma, all-single). Per CTA: 128 q rows; 8 warps x 16q x 64k,
// two independent 32-key halves (MUFU of one overlaps HMMA of the other).
// Bitmask masking, scalar Zm. Q pre-scaled 0.125*log2e; e = ex2(s).
// 3-deep KV ring -> ONE barrier per iteration.
// smem halves: Q@0 (9216), 3 KV buffers @9216 stride 9216 (K@0, V@4608).
// ---------------------------------------------------------------------------
#define ATTN_SMEM ((9216 + 3 * 9216) * 2)

__device__ __forceinline__ void attn_issue_kv(int b, int h, int it, uint32_t sb,
                                              int p, int tid) {
    const int k0 = it * 64;
    #pragma unroll
    for (int j = 0; j < 4; j++) {
        int linear = tid + j * 256;
        int arr = linear >> 9, rem = linear & 511;
        int r = rem >> 3, c = rem & 7;
        const __half* src = arr
            ? g_vh + (size_t)(b * S + k0 + r) * 1024 + h * 64 + c * 8
            : g_qk + (size_t)(b * S + k0 + r) * 2048 + D + h * 64 + c * 8;
        cp16(sb + (uint32_t)(9216 + p * 9216 + arr * 4608 + r * 72 + c * 8) * 2, src);
    }
}

__global__ __launch_bounds__(256, 2)
void attn_mma() {
    extern __shared__ __half smh[];
    const int tid = threadIdx.x;
    const int wid = tid >> 5, lane = tid & 31;
    const int b = blockIdx.z, h = blockIdx.y;
    const int q0 = blockIdx.x * 128;
    const uint32_t sb = smem_u32(smh);

    // Q -> smem (same commit group as iter-0 K/V)
    #pragma unroll
    for (int j = 0; j < 4; j++) {
        int linear = tid + j * 256;
        int r = linear >> 3, c = linear & 7;
        cp16(sb + (uint32_t)(r * 72 + c * 8) * 2,
             g_qk + (size_t)(b * S + q0 + r) * 2048 + h * 64 + c * 8);
    }
    attn_issue_kv(b, h, 0, sb, 0, tid);
    cp_commit();

    float Oc[8][4] = {};
    float zm0 = 0.f, zm1 = 0.f;
    uint32_t qh[4][4];   // static Q frags, loaded once at it==0
    int p = 0;

    const uint32_t qrow_off = (uint32_t)((wid * 16 + (lane & 15)) * 72 + (lane >> 4) * 8);
    const uint32_t* mp = g_mb
        + (size_t)((b * 128 + blockIdx.x * 8 + wid) * 8 + (lane >> 2)) * 128 + (lane & 3);

    const int niter = S / 64;
    for (int it = 0; it < niter; ++it) {
        const int pn = (p + 1 == 3) ? 0 : p + 1;
        if (it + 1 < niter) {
            attn_issue_kv(b, h, it + 1, sb, pn, tid);
            cp_commit();
            cp_wait1();
        } else {
            cp_wait0();
        }

        const uint32_t mw = mp[it * 4];   // 4B bitmask, prefetched pre-barrier

        __syncthreads();   // KV buffer p (and at it=0, Q) ready; single barrier

        if (it == 0) {
            #pragma unroll
            for (int kk = 0; kk < 4; kk++)
                ldsm_x4(qh[kk], sb + (qrow_off + (uint32_t)(kk * 16)) * 2);
        }

        const uint32_t kvb = 9216u + (uint32_t)p * 9216u;

        // two independent 32-key halves -> MUFU of one overlaps HMMA of other
        #pragma unroll
        for (int hf = 0; hf < 2; hf++) {
            // scores for keys [hf*32, hf*32+32)
            float sc[4][4] = {};
            #pragma unroll
            for (int jj = 0; jj < 2; jj++) {
                const int jp = hf * 2 + jj;
                const uint32_t krow = (uint32_t)((jp * 16 + (lane & 15)) * 72
                                                 + (lane >> 4) * 8);
                #pragma unroll
                for (int kk = 0; kk < 4; kk++) {
                    uint32_t kh[4];
                    ldsm_x4(kh, sb + (kvb + krow + (uint32_t)(kk * 16)) * 2);
                    mma16816h(sc[jj * 2 + 0], qh[kk], kh[0], kh[2]);
                    mma16816h(sc[jj * 2 + 1], qh[kk], kh[1], kh[3]);
                }
            }

            // ex2 + bit-mask + Zm + pack P into a-frags
            uint32_t pa[2][4];
            #pragma unroll
            for (int j = 0; j < 4; j++) {
                const int jg = hf * 4 + j;
                float e0 = ex2(sc[j][0]);
                float e1 = ex2(sc[j][1]);
                float e2 = ex2(sc[j][2]);
                float e3 = ex2(sc[j][3]);
                float em0 = (mw & (1u << (2 * jg)))      ? e0 : 0.0f;
                float em1 = (mw & (1u << (2 * jg + 1)))  ? e1 : 0.0f;
                float em2 = (mw & (1u << (16 + 2 * jg))) ? e2 : 0.0f;
                float em3 = (mw & (1u << (17 + 2 * jg))) ? e3 : 0.0f;
                zm0 += em0 + em1; zm1 += em2 + em3;
                pa[j >> 1][(j & 1) * 2 + 0] = h2pack_sat(em0, em1);
                pa[j >> 1][(j & 1) * 2 + 1] = h2pack_sat(em2, em3);
            }

            // PV for key rows [hf*32, hf*32+32)
            #pragma unroll
            for (int j2 = 0; j2 < 2; j2++) {
                const int j2g = hf * 2 + j2;
                const uint32_t vrow = (uint32_t)((j2g * 16 + ((lane >> 3) & 1) * 8
                                                  + (lane & 7)) * 72 + (lane >> 4) * 8);
                #pragma unroll
                for (int ndp = 0; ndp < 4; ndp++) {
                    uint32_t vh[4];
                    ldsm_x4_t(vh, sb + (kvb + 4608u + vrow + (uint32_t)(ndp * 16)) * 2);
                    mma16816h(Oc[ndp * 2 + 0], pa[j2], vh[0], vh[1]);
                    mma16816h(Oc[ndp * 2 + 1], pa[j2], vh[2], vh[3]);
                }
            }
        }
        p = pn;
    }

    // quad reduce Zm (lanes sharing lane>>2 hold the same rows)
    #pragma unroll
    for (int off = 1; off < 4; off <<= 1) {
        zm0 += __shfl_xor_sync(0xffffffffu, zm0, off);
        zm1 += __shfl_xor_sync(0xffffffffu, zm1, off);
    }
    const float inv0 = 1.0f / zm0;
    const float inv1 = 1.0f / zm1;

    const int row = b * S + q0 + wid * 16 + (lane >> 2);
    #pragma unroll
    for (int nd = 0; nd < 8; nd++) {
        const int col = h * 64 + nd * 8 + (lane & 3) * 2;
        single_store_h(g_ath, (size_t)row * D + col,
                       Oc[nd][0] * inv0, Oc[nd][1] * inv0);
        single_store_h(g_ath, (size_t)(row + 8) * D + col,
                       Oc[nd][2] * inv1, Oc[nd][3] * inv1);
    }
}

// ---------------------------------------------------------------------------
extern "C" void kernel_launch(void* const* d_in, const int* in_sizes, int n_in,
                              void* d_out, int out_size) {
    const float* x         = (const float*)d_in[0];  // [B,S,D]
    const float* Vin       = (const float*)d_in[1];  // [B,S,H,HD]
    const float* Min       = (const float*)d_in[2];  // [B,S,S]
    const float* in_proj_w = (const float*)d_in[3];  // [3D,D]
    const float* in_proj_b = (const float*)d_in[4];  // [3D]
    const float* out_w     = (const float*)d_in[5];  // [D,D]
    const float* out_b     = (const float*)d_in[6];  // [D]
    float* out             = (float*)d_out;          // [B,S,D]

    __half *xh, *w1, *w3, *qk, *ath;
    cudaGetSymbolAddress((void**)&xh,  g_xh);
    cudaGetSymbolAddress((void**)&w1,  g_w1);
    cudaGetSymbolAddress((void**)&w3,  g_w3);
    cudaGetSymbolAddress((void**)&qk,  g_qk);
    cudaGetSymbolAddress((void**)&ath, g_ath);

    cudaFuncSetAttribute(mma_gemm, cudaFuncAttributeMaxDynamicSharedMemorySize, GEMM_SMEM);
    cudaFuncSetAttribute(attn_mma, cudaFuncAttributeMaxDynamicSharedMemorySize, ATTN_SMEM);

    const int Mtot = Bsz * S;  // 4096

    // fused conversions + mask bit-pack (one launch)
    conv_all<<<(CNTOT + 255) / 256, 256>>>(x, in_proj_w, out_w, Vin, Min);

    // Stage 1: [Q|K] = x @ in_proj_w[0:2D]^T + b -> fp16 single (Q scaled)
    mma_gemm<<<dim3((2 * D) / 128, Mtot / 128), 256, GEMM_SMEM>>>(
        xh, w1, in_proj_b, nullptr, qk, D, 2 * D, 1);

    // Stage 2: masked-renormalized attention -> fp16 single [4096][1024]
    attn_mma<<<dim3(S / 128, H, Bsz), 256, ATTN_SMEM>>>();

    // Stage 3: out = attn @ out_w^T + out_b  (fp32)
    mma_gemm<<<dim3(D / 128, Mtot / 128), 256, GEMM_SMEM>>>(
        ath, w3, out_b, out, nullptr, D, D, 0);
}